// round 5
// baseline (speedup 1.0000x reference)
#include <cuda_runtime.h>

#define NNODES 100000
#define NEDGES 1200000
#define D 64
#define D4 16              // D/4
#define MT 128             // nodes per GEMM block
#define ALPHA 0.01f
#define BN_EPS 1e-5f

// -------- scratch (static device globals; no allocations allowed) --------
__device__ __align__(16) float g_deg[NNODES];
__device__ __align__(16) float g_dis[NNODES];
__device__ __align__(16) float g_h  [(size_t)NNODES * D];
__device__ __align__(16) float g_agg[(size_t)NNODES * D];
__device__ __align__(16) float g_sum[D];
__device__ __align__(16) float g_sumsq[D];
__device__ int  g_cnt[NNODES];
__device__ int  g_excl[NNODES];
__device__ int  g_rowstart[NNODES + 1];
__device__ int  g_cursor[NNODES];
__device__ int  g_bsum[512];
__device__ int  g_boff[512];
__device__ __align__(8) int2 g_edge[NEDGES];   // (src_row, w_bits) sorted by dst

// -------- B0: reset per-replay state -------------------------------------
__global__ void k_b0(int n) {
    int i = blockIdx.x * blockDim.x + threadIdx.x;
    if (i < n) { g_cnt[i] = 0; g_deg[i] = 0.0f; }
    if (i < D) { g_sum[i] = 0.0f; g_sumsq[i] = 0.0f; }
}

// -------- B1: per-node in-edge count + weighted degree -------------------
__global__ void k_count(const int* __restrict__ col, const float* __restrict__ w, int E) {
    int i = blockIdx.x * blockDim.x + threadIdx.x;
    if (i < E) {
        int c = col[i];
        atomicAdd(&g_cnt[c], 1);
        atomicAdd(&g_deg[c], w[i]);
    }
}

// -------- S1: per-block inclusive scan of counts -------------------------
__global__ void k_scan1(int n) {
    __shared__ int sm[256];
    const int t = threadIdx.x;
    const int i = blockIdx.x * 256 + t;
    const int v = (i < n) ? g_cnt[i] : 0;
    int incl = v;
    sm[t] = incl; __syncthreads();
#pragma unroll
    for (int off = 1; off < 256; off <<= 1) {
        int add = (t >= off) ? sm[t - off] : 0;
        __syncthreads();
        incl += add; sm[t] = incl;
        __syncthreads();
    }
    if (i < n) g_excl[i] = incl - v;
    if (t == 255) g_bsum[blockIdx.x] = incl;
}

// -------- S2: scan the block sums (single block) -------------------------
__global__ void k_scan2(int nb) {
    __shared__ int sm[512];
    const int t = threadIdx.x;
    const int v = (t < nb) ? g_bsum[t] : 0;
    int incl = v;
    sm[t] = incl; __syncthreads();
#pragma unroll
    for (int off = 1; off < 512; off <<= 1) {
        int add = (t >= off) ? sm[t - off] : 0;
        __syncthreads();
        incl += add; sm[t] = incl;
        __syncthreads();
    }
    g_boff[t] = incl - v;
}

// -------- S3: finalize row_start, cursor, dis ----------------------------
__global__ void k_scan3(int n, int E) {
    int i = blockIdx.x * blockDim.x + threadIdx.x;
    if (i < n) {
        int rs = g_excl[i] + g_boff[i >> 8];
        g_rowstart[i] = rs;
        g_cursor[i]   = rs;
        g_dis[i] = rsqrtf(1.0f + g_deg[i]);   // self-loop weight 1 included
    }
    if (i == 0) g_rowstart[n] = E;
}

// -------- F: bin edges by destination ------------------------------------
__global__ void k_fill(const int* __restrict__ row, const int* __restrict__ col,
                       const float* __restrict__ w, int E) {
    int e = blockIdx.x * blockDim.x + threadIdx.x;
    if (e < E) {
        int c = col[e];
        int pos = atomicAdd(&g_cursor[c], 1);
        g_edge[pos] = make_int2(row[e], __float_as_int(w[e]));
    }
}

// -------- K3: h = x @ W (h only; self-loop handled in pull) --------------
__global__ void __launch_bounds__(256) k_gemm(const float* __restrict__ x,
                                              const float* __restrict__ W, int n) {
    __shared__ float  xs[MT * 64];        // 32 KB, row-major [m][k]
    __shared__ float4 Ws[64 * D4];        // 16 KB

    const int tid = threadIdx.x;
    const int tx = tid & 15;
    const int ty = tid >> 4;

    const float4* W4 = (const float4*)W;
#pragma unroll
    for (int i = 0; i < 4; i++) Ws[tid + i * 256] = W4[tid + i * 256];

    const int m0 = blockIdx.x * MT;
#pragma unroll
    for (int t = 0; t < 8; t++) {
        const int idx = tid + t * 256;
        const int node = m0 + (idx >> 4);
        float4 v = make_float4(0.f, 0.f, 0.f, 0.f);
        if (node < n) v = ((const float4*)x)[node * D4 + (idx & 15)];
        ((float4*)xs)[idx] = v;
    }
    __syncthreads();

    float4 acc[8];
#pragma unroll
    for (int i = 0; i < 8; i++) acc[i] = make_float4(0.f, 0.f, 0.f, 0.f);

    const float* xrow = xs + (ty * 8) * 64;
#pragma unroll 8
    for (int k = 0; k < 64; k++) {
        const float4 w = Ws[k * D4 + tx];
#pragma unroll
        for (int i = 0; i < 8; i++) {
            const float a = xrow[i * 64 + k];   // broadcast across tx lanes
            acc[i].x = fmaf(a, w.x, acc[i].x);
            acc[i].y = fmaf(a, w.y, acc[i].y);
            acc[i].z = fmaf(a, w.z, acc[i].z);
            acc[i].w = fmaf(a, w.w, acc[i].w);
        }
    }

#pragma unroll
    for (int i = 0; i < 8; i++) {
        const int node = m0 + ty * 8 + i;
        if (node < n) ((float4*)g_h)[node * D4 + tx] = acc[i];
    }
}

// -------- P: pull-aggregate + self-loop + fused BN stats -----------------
// 256 threads = 16 nodes x 16 lanes; lane l owns cols 4l..4l+3.
__global__ void __launch_bounds__(256) k_pull(int n) {
    __shared__ float4 ss [16][16];
    __shared__ float4 ss2[16][16];
    const int tid  = threadIdx.x;
    const int l    = tid & 15;
    const int slot = tid >> 4;
    const int node = blockIdx.x * 16 + slot;

    float4 acc = make_float4(0.f, 0.f, 0.f, 0.f);
    if (node < n) {
        const int e0 = g_rowstart[node];
        const int e1 = g_rowstart[node + 1];
        const float dc = g_dis[node];
        const float4 hv = ((const float4*)g_h)[node * D4 + l];
        // self-loop: h*dc (final *dc below gives h/deg)
        acc = make_float4(hv.x * dc, hv.y * dc, hv.z * dc, hv.w * dc);

        int j = e0;
        int2 ed = (j < e1) ? g_edge[j] : make_int2(0, 0);
        while (j < e1) {
            const int2 cur = ed;
            ++j;
            if (j < e1) ed = g_edge[j];            // prefetch next edge
            const float nm = g_dis[cur.x] * __int_as_float(cur.y);
            const float4 h2 = ((const float4*)g_h)[cur.x * D4 + l];
            acc.x = fmaf(nm, h2.x, acc.x);
            acc.y = fmaf(nm, h2.y, acc.y);
            acc.z = fmaf(nm, h2.z, acc.z);
            acc.w = fmaf(nm, h2.w, acc.w);
        }
        acc.x *= dc; acc.y *= dc; acc.z *= dc; acc.w *= dc;
        ((float4*)g_agg)[node * D4 + l] = acc;
    }

    // fused BN statistics (zeros for node >= n)
    ss [slot][l] = acc;
    ss2[slot][l] = make_float4(acc.x * acc.x, acc.y * acc.y,
                               acc.z * acc.z, acc.w * acc.w);
    __syncthreads();
#pragma unroll
    for (int off = 8; off > 0; off >>= 1) {
        if (slot < off) {
            float4 a = ss[slot + off][l], b = ss2[slot + off][l];
            float4 u = ss[slot][l],      v = ss2[slot][l];
            u.x += a.x; u.y += a.y; u.z += a.z; u.w += a.w;
            v.x += b.x; v.y += b.y; v.z += b.z; v.w += b.w;
            ss[slot][l] = u; ss2[slot][l] = v;
        }
        __syncthreads();
    }
    if (slot == 0) {
        const float4 u = ss[0][l], v = ss2[0][l];
        atomicAdd(&g_sum[l * 4 + 0], u.x); atomicAdd(&g_sumsq[l * 4 + 0], v.x);
        atomicAdd(&g_sum[l * 4 + 1], u.y); atomicAdd(&g_sumsq[l * 4 + 1], v.y);
        atomicAdd(&g_sum[l * 4 + 2], u.z); atomicAdd(&g_sumsq[l * 4 + 2], v.z);
        atomicAdd(&g_sum[l * 4 + 3], u.w); atomicAdd(&g_sumsq[l * 4 + 3], v.w);
    }
}

// -------- K6: BatchNorm (biased var) + LeakyReLU -------------------------
// +b before BN cancels exactly in (x - mean), so b is skipped.
__global__ void k_bn(const float* __restrict__ gamma, const float* __restrict__ beta,
                     float* __restrict__ out, int n) {
    const int gid = blockIdx.x * blockDim.x + threadIdx.x;
    if (gid >= n * D4) return;
    const int c4 = gid & 15;
    float4 v  = ((const float4*)g_agg)[gid];
    const float4 sm = ((const float4*)g_sum)[c4];
    const float4 sq = ((const float4*)g_sumsq)[c4];
    const float4 gm = ((const float4*)gamma)[c4];
    const float4 bt = ((const float4*)beta)[c4];
    const float invN = 1.0f / (float)n;

    float m, var, sc, o;
    m = sm.x * invN; var = fmaf(-m, m, sq.x * invN); sc = rsqrtf(var + BN_EPS) * gm.x;
    o = (v.x - m) * sc + bt.x; v.x = (o >= 0.f) ? o : ALPHA * o;
    m = sm.y * invN; var = fmaf(-m, m, sq.y * invN); sc = rsqrtf(var + BN_EPS) * gm.y;
    o = (v.y - m) * sc + bt.y; v.y = (o >= 0.f) ? o : ALPHA * o;
    m = sm.z * invN; var = fmaf(-m, m, sq.z * invN); sc = rsqrtf(var + BN_EPS) * gm.z;
    o = (v.z - m) * sc + bt.z; v.z = (o >= 0.f) ? o : ALPHA * o;
    m = sm.w * invN; var = fmaf(-m, m, sq.w * invN); sc = rsqrtf(var + BN_EPS) * gm.w;
    o = (v.w - m) * sc + bt.w; v.w = (o >= 0.f) ? o : ALPHA * o;

    ((float4*)out)[gid] = v;
}

extern "C" void kernel_launch(void* const* d_in, const int* in_sizes, int n_in,
                              void* d_out, int out_size) {
    const float* x     = (const float*)d_in[0];
    const int*   eidx  = (const int*)d_in[1];
    const float* eattr = (const float*)d_in[2];
    const float* W     = (const float*)d_in[3];
    // d_in[4] = b : cancels in BatchNorm, intentionally unused
    const float* gamma = (const float*)d_in[5];
    const float* beta  = (const float*)d_in[6];
    float* out = (float*)d_out;

    const int N = in_sizes[0] / D;       // 100000
    const int E = in_sizes[2];           // 1200000
    const int* row = eidx;
    const int* col = eidx + E;
    const int NB = (N + 255) / 256;      // 391 (<= 512)

    k_b0   <<<NB, 256>>>(N);
    k_count<<<(E + 255) / 256, 256>>>(col, eattr, E);
    k_scan1<<<NB, 256>>>(N);
    k_scan2<<<1, 512>>>(NB);
    k_scan3<<<NB, 256>>>(N, E);
    k_gemm <<<(N + MT - 1) / MT, 256>>>(x, W, N);
    k_fill <<<(E + 255) / 256, 256>>>(row, col, eattr, E);
    k_pull <<<(N + 15) / 16, 256>>>(N);
    k_bn   <<<(N * D4 + 255) / 256, 256>>>(gamma, beta, out, N);
}

// round 6
// speedup vs baseline: 1.6237x; 1.6237x over previous
#include <cuda_runtime.h>

#define NNODES 100000
#define NEDGES 1200000
#define D 64
#define D4 16              // D/4
#define MT 128             // nodes per GEMM block
#define ALPHA 0.01f
#define BN_EPS 1e-5f

// -------- scratch (static device globals; no allocations allowed) --------
__device__ __align__(16) float g_deg[NNODES];
__device__ __align__(16) float g_dis[NNODES];
__device__ __align__(16) float g_h  [(size_t)NNODES * D];
__device__ __align__(16) float g_agg[(size_t)NNODES * D];
__device__ __align__(16) float g_sum[D];
__device__ __align__(16) float g_sumsq[D];
__device__ int  g_cnt[NNODES];
__device__ int  g_excl[NNODES];
__device__ int  g_rowstart[NNODES + 1];
__device__ int  g_cursor[NNODES];
__device__ int  g_bsum[512];
__device__ int  g_boff[512];
__device__ __align__(8) int2 g_edge[NEDGES];   // (src_row, w_bits) sorted by dst

// -------- K3: h = x @ W (pure; no graph deps, launched first) ------------
__global__ void __launch_bounds__(256) k_gemm(const float* __restrict__ x,
                                              const float* __restrict__ W, int n) {
    __shared__ float  xs[MT * 64];        // 32 KB, row-major [m][k]
    __shared__ float4 Ws[64 * D4];        // 16 KB

    const int tid = threadIdx.x;
    const int tx = tid & 15;
    const int ty = tid >> 4;

    const float4* W4 = (const float4*)W;
#pragma unroll
    for (int i = 0; i < 4; i++) Ws[tid + i * 256] = W4[tid + i * 256];

    const int m0 = blockIdx.x * MT;
#pragma unroll
    for (int t = 0; t < 8; t++) {
        const int idx = tid + t * 256;
        const int node = m0 + (idx >> 4);
        float4 v = make_float4(0.f, 0.f, 0.f, 0.f);
        if (node < n) v = ((const float4*)x)[node * D4 + (idx & 15)];
        ((float4*)xs)[idx] = v;
    }
    __syncthreads();

    float4 acc[8];
#pragma unroll
    for (int i = 0; i < 8; i++) acc[i] = make_float4(0.f, 0.f, 0.f, 0.f);

    const float* xrow = xs + (ty * 8) * 64;
#pragma unroll 8
    for (int k = 0; k < 64; k++) {
        const float4 w = Ws[k * D4 + tx];
#pragma unroll
        for (int i = 0; i < 8; i++) {
            const float a = xrow[i * 64 + k];   // broadcast across tx lanes
            acc[i].x = fmaf(a, w.x, acc[i].x);
            acc[i].y = fmaf(a, w.y, acc[i].y);
            acc[i].z = fmaf(a, w.z, acc[i].z);
            acc[i].w = fmaf(a, w.w, acc[i].w);
        }
    }

#pragma unroll
    for (int i = 0; i < 8; i++) {
        const int node = m0 + ty * 8 + i;
        if (node < n) ((float4*)g_h)[node * D4 + tx] = acc[i];
    }
}

// -------- B0: reset per-replay state -------------------------------------
__global__ void k_b0(int n) {
    int i = blockIdx.x * blockDim.x + threadIdx.x;
    if (i < n) { g_cnt[i] = 0; g_deg[i] = 0.0f; }
    if (i < D) { g_sum[i] = 0.0f; g_sumsq[i] = 0.0f; }
}

// -------- B1: per-node in-edge count + weighted degree -------------------
__global__ void k_count(const int* __restrict__ col, const float* __restrict__ w, int E) {
    int i = blockIdx.x * blockDim.x + threadIdx.x;
    if (i < E) {
        int c = col[i];
        atomicAdd(&g_cnt[c], 1);
        atomicAdd(&g_deg[c], w[i]);
    }
}

// -------- S1: per-block inclusive scan of counts -------------------------
__global__ void k_scan1(int n) {
    __shared__ int sm[256];
    const int t = threadIdx.x;
    const int i = blockIdx.x * 256 + t;
    const int v = (i < n) ? g_cnt[i] : 0;
    int incl = v;
    sm[t] = incl; __syncthreads();
#pragma unroll
    for (int off = 1; off < 256; off <<= 1) {
        int add = (t >= off) ? sm[t - off] : 0;
        __syncthreads();
        incl += add; sm[t] = incl;
        __syncthreads();
    }
    if (i < n) g_excl[i] = incl - v;
    if (t == 255) g_bsum[blockIdx.x] = incl;
}

// -------- S2: scan the block sums (single block) -------------------------
__global__ void k_scan2(int nb) {
    __shared__ int sm[512];
    const int t = threadIdx.x;
    const int v = (t < nb) ? g_bsum[t] : 0;
    int incl = v;
    sm[t] = incl; __syncthreads();
#pragma unroll
    for (int off = 1; off < 512; off <<= 1) {
        int add = (t >= off) ? sm[t - off] : 0;
        __syncthreads();
        incl += add; sm[t] = incl;
        __syncthreads();
    }
    g_boff[t] = incl - v;
}

// -------- S3: finalize row_start, cursor, dis ----------------------------
__global__ void k_scan3(int n, int E) {
    int i = blockIdx.x * blockDim.x + threadIdx.x;
    if (i < n) {
        int rs = g_excl[i] + g_boff[i >> 8];
        g_rowstart[i] = rs;
        g_cursor[i]   = rs;
        g_dis[i] = rsqrtf(1.0f + g_deg[i]);   // self-loop weight 1 included
    }
    if (i == 0) g_rowstart[n] = E;
}

// -------- F: bin edges by destination ------------------------------------
__global__ void k_fill(const int* __restrict__ row, const int* __restrict__ col,
                       const float* __restrict__ w, int E) {
    int e = blockIdx.x * blockDim.x + threadIdx.x;
    if (e < E) {
        int c = col[e];
        int pos = atomicAdd(&g_cursor[c], 1);
        g_edge[pos] = make_int2(row[e], __float_as_int(w[e]));
    }
}

// -------- P: pull-aggregate v3 — ONE WARP PER NODE -----------------------
// 32 lanes = 2 edge-parity halves x 16 col4 lanes. 2-pair-deep prefetch so
// gathers pipeline; cross-half combine via shfl.xor(16). No smem, low regs.
__global__ void __launch_bounds__(256) k_pull(int n) {
    const int wib  = threadIdx.x >> 5;
    const int lane = threadIdx.x & 31;
    const int node = blockIdx.x * 8 + wib;
    if (node >= n) return;                 // warp-uniform exit
    const int hp = lane >> 4;              // edge parity (0/1)
    const int l  = lane & 15;              // col4 group

    const int   e0 = g_rowstart[node];
    const int   e1 = g_rowstart[node + 1];
    const float dc = g_dis[node];
    const float4* H = (const float4*)g_h;

    // self-loop: acc_final = dc*(sum + dc*h) = sum*dc + h/deg. Half 0 seeds.
    float4 acc = make_float4(0.f, 0.f, 0.f, 0.f);
    if (hp == 0) {
        const float4 hv = H[node * D4 + l];
        acc = make_float4(hv.x * dc, hv.y * dc, hv.z * dc, hv.w * dc);
    }

    int j = e0 + hp;                       // this half's edge stream, stride 2
    int2 ea = make_int2(0, 0), eb = make_int2(0, 0);
    if (j < e1)     ea = g_edge[j];
    if (j + 2 < e1) eb = g_edge[j + 2];
    while (j < e1) {
        const int2 cur = ea;
        ea = eb;
        if (j + 4 < e1) eb = g_edge[j + 4];          // prefetch 2 pairs ahead
        const float  nm = g_dis[cur.x] * __int_as_float(cur.y);
        const float4 hr = H[cur.x * D4 + l];
        acc.x = fmaf(nm, hr.x, acc.x);
        acc.y = fmaf(nm, hr.y, acc.y);
        acc.z = fmaf(nm, hr.z, acc.z);
        acc.w = fmaf(nm, hr.w, acc.w);
        j += 2;
    }

    // combine the two halves (lane <-> lane^16 hold same cols)
    acc.x += __shfl_xor_sync(0xffffffffu, acc.x, 16);
    acc.y += __shfl_xor_sync(0xffffffffu, acc.y, 16);
    acc.z += __shfl_xor_sync(0xffffffffu, acc.z, 16);
    acc.w += __shfl_xor_sync(0xffffffffu, acc.w, 16);

    if (hp == 0) {
        acc.x *= dc; acc.y *= dc; acc.z *= dc; acc.w *= dc;
        ((float4*)g_agg)[node * D4 + l] = acc;
    }
}

// -------- K5: per-column sum / sumsq (proven R2 version) -----------------
__global__ void k_stats(int n) {
    __shared__ float4 ss [16][16];
    __shared__ float4 ss2[16][16];
    const int tid = threadIdx.x;
    const int c4 = tid & 15;
    const int rl = tid >> 4;
    float4 s  = make_float4(0.f, 0.f, 0.f, 0.f);
    float4 s2 = make_float4(0.f, 0.f, 0.f, 0.f);
    for (int r = blockIdx.x * 16 + rl; r < n; r += gridDim.x * 16) {
        const float4 v = ((const float4*)g_agg)[r * D4 + c4];
        s.x += v.x; s.y += v.y; s.z += v.z; s.w += v.w;
        s2.x = fmaf(v.x, v.x, s2.x);
        s2.y = fmaf(v.y, v.y, s2.y);
        s2.z = fmaf(v.z, v.z, s2.z);
        s2.w = fmaf(v.w, v.w, s2.w);
    }
    ss[rl][c4] = s; ss2[rl][c4] = s2;
    __syncthreads();
#pragma unroll
    for (int off = 8; off > 0; off >>= 1) {
        if (rl < off) {
            float4 a = ss[rl + off][c4], b = ss2[rl + off][c4];
            float4 u = ss[rl][c4],      v = ss2[rl][c4];
            u.x += a.x; u.y += a.y; u.z += a.z; u.w += a.w;
            v.x += b.x; v.y += b.y; v.z += b.z; v.w += b.w;
            ss[rl][c4] = u; ss2[rl][c4] = v;
        }
        __syncthreads();
    }
    if (rl == 0) {
        const float4 u = ss[0][c4], v = ss2[0][c4];
        atomicAdd(&g_sum[c4 * 4 + 0], u.x); atomicAdd(&g_sumsq[c4 * 4 + 0], v.x);
        atomicAdd(&g_sum[c4 * 4 + 1], u.y); atomicAdd(&g_sumsq[c4 * 4 + 1], v.y);
        atomicAdd(&g_sum[c4 * 4 + 2], u.z); atomicAdd(&g_sumsq[c4 * 4 + 2], v.z);
        atomicAdd(&g_sum[c4 * 4 + 3], u.w); atomicAdd(&g_sumsq[c4 * 4 + 3], v.w);
    }
}

// -------- K6: BatchNorm (biased var) + LeakyReLU -------------------------
// +b before BN cancels exactly in (x - mean), so b is skipped.
__global__ void k_bn(const float* __restrict__ gamma, const float* __restrict__ beta,
                     float* __restrict__ out, int n) {
    const int gid = blockIdx.x * blockDim.x + threadIdx.x;
    if (gid >= n * D4) return;
    const int c4 = gid & 15;
    float4 v  = ((const float4*)g_agg)[gid];
    const float4 sm = ((const float4*)g_sum)[c4];
    const float4 sq = ((const float4*)g_sumsq)[c4];
    const float4 gm = ((const float4*)gamma)[c4];
    const float4 bt = ((const float4*)beta)[c4];
    const float invN = 1.0f / (float)n;

    float m, var, sc, o;
    m = sm.x * invN; var = fmaf(-m, m, sq.x * invN); sc = rsqrtf(var + BN_EPS) * gm.x;
    o = (v.x - m) * sc + bt.x; v.x = (o >= 0.f) ? o : ALPHA * o;
    m = sm.y * invN; var = fmaf(-m, m, sq.y * invN); sc = rsqrtf(var + BN_EPS) * gm.y;
    o = (v.y - m) * sc + bt.y; v.y = (o >= 0.f) ? o : ALPHA * o;
    m = sm.z * invN; var = fmaf(-m, m, sq.z * invN); sc = rsqrtf(var + BN_EPS) * gm.z;
    o = (v.z - m) * sc + bt.z; v.z = (o >= 0.f) ? o : ALPHA * o;
    m = sm.w * invN; var = fmaf(-m, m, sq.w * invN); sc = rsqrtf(var + BN_EPS) * gm.w;
    o = (v.w - m) * sc + bt.w; v.w = (o >= 0.f) ? o : ALPHA * o;

    ((float4*)out)[gid] = v;
}

extern "C" void kernel_launch(void* const* d_in, const int* in_sizes, int n_in,
                              void* d_out, int out_size) {
    const float* x     = (const float*)d_in[0];
    const int*   eidx  = (const int*)d_in[1];
    const float* eattr = (const float*)d_in[2];
    const float* W     = (const float*)d_in[3];
    // d_in[4] = b : cancels in BatchNorm, intentionally unused
    const float* gamma = (const float*)d_in[5];
    const float* beta  = (const float*)d_in[6];
    float* out = (float*)d_out;

    const int N = in_sizes[0] / D;       // 100000
    const int E = in_sizes[2];           // 1200000
    const int* row = eidx;
    const int* col = eidx + E;
    const int NB = (N + 255) / 256;      // 391 (<= 512)

    k_gemm <<<(N + MT - 1) / MT, 256>>>(x, W, N);
    k_b0   <<<NB, 256>>>(N);
    k_count<<<(E + 255) / 256, 256>>>(col, eattr, E);
    k_scan1<<<NB, 256>>>(N);
    k_scan2<<<1, 512>>>(NB);
    k_scan3<<<NB, 256>>>(N, E);
    k_fill <<<(E + 255) / 256, 256>>>(row, col, eattr, E);
    k_pull <<<(N + 7) / 8, 256>>>(N);
    k_stats<<<592, 256>>>(N);
    k_bn   <<<(N * D4 + 255) / 256, 256>>>(gamma, beta, out, N);
}